// round 12
// baseline (speedup 1.0000x reference)
#include <cuda_runtime.h>

// Problem constants (fixed by dataset)
#define D_MODEL 1024
#define ADAPT   128
#define NUM_LIB 8
#define NPAIR   64
#define MAXB    1024
#define KC      8        // k-split for gemm1 (128 k per CTA)
#define KCH     128
#define DC      128      // d-cols per gemm2 CTA
#define NST     16       // stages per slab (8 lines x 128 cols = 4 KB each)
#define RT      32       // row capacity per tile (covers whole pair)
#define RSF     36       // float stride per k/a line (aligned, 2-way STS)
#define RING    6        // cp.async ring depth

typedef unsigned long long ull;

// Packed fp32x2 ops (sm_10x)
#define FMA2(d,a,b,c) asm("fma.rn.f32x2 %0, %1, %2, %3;":"=l"(d):"l"(a),"l"(b),"l"(c))
#define PACK2(d,s)    asm("mov.b64 %0, {%1, %1};":"=l"(d):"f"(s))
#define UNPK2(lo,hi,s) asm("mov.b64 {%0, %1}, %2;":"=f"(lo),"=f"(hi):"l"(s))
// cp.async 16B, L1-bypass
#define CP16(dst,src) asm volatile("cp.async.cg.shared.global [%0], [%1], 16;"::"r"(dst),"l"(src))
#define CPCOMMIT()    asm volatile("cp.async.commit_group;")
#define CPWAIT4()     asm volatile("cp.async.wait_group 4;")

// Device scratch (no allocations allowed)
__device__ int   g_cnt[NPAIR];
__device__ int   g_done[NPAIR];
__device__ int   g_rows[NPAIR][MAXB];
__device__ float g_hp[KC][MAXB * ADAPT];   // K-split partial pre-activations
__device__ float g_h[MAXB * ADAPT];        // relu(sum + b1)

// ---------------------------------------------------------------------------
__global__ void k_build(const int* __restrict__ src, const int* __restrict__ tgt, int B) {
    int t = threadIdx.x;
    if (t < NPAIR) { g_cnt[t] = 0; g_done[t] = 0; }
    __syncthreads();
    if (t < B) {
        int s = src[t], g = tgt[t];
        if (s != g) {
            int p = s * NUM_LIB + g;
            int slot = atomicAdd(&g_cnt[p], 1);
            g_rows[p][slot] = t;
        }
    }
}

// ---------------------------------------------------------------------------
__global__ void __launch_bounds__(256)
k_copy(const float* __restrict__ x,
       const int* __restrict__ src, const int* __restrict__ tgt,
       float* __restrict__ out, int B) {
    for (int b = blockIdx.x; b < B; b += gridDim.x) {
        if (src[b] != tgt[b]) continue;
        const float4* xi = (const float4*)(x + (size_t)b * D_MODEL);
        float4* yo = (float4*)(out + (size_t)b * D_MODEL);
        yo[threadIdx.x] = xi[threadIdx.x];
    }
}

// ---------------------------------------------------------------------------
// GEMM1 (k-split): g_hp[kz][row, a] = x[row, kz*128:+128] . W1[p, slice, a]
// grid (64, 8), 128 thr. Thread: a-quad tq = t&31, warp rg = t>>5 -> 8 rows.
// acc packs ROW pairs; weights lane-duplicated via PACK2 (alu pipe).
// Depth-6 cp.async weight ring; x staged as plain floats [k][row].
// LAST CTA of each pair (g_done ticket) reduces 8 partials -> g_h = relu(.+b1).
// ---------------------------------------------------------------------------
__global__ void __launch_bounds__(128, 5)
k_gemm1(const float* __restrict__ x, const float* __restrict__ W1,
        const float* __restrict__ b1) {
    extern __shared__ __align__(16) char smx[];
    float* xs = (float*)smx;                      // [128 k][RSF] (18 KB)
    float* ws = (float*)(smx + KCH * RSF * 4);    // ring [6][8*128] (24 KB)
    __shared__ int sticket;
    int p  = blockIdx.x;
    int kz = blockIdx.y;
    int n = g_cnt[p];
    if (n == 0) return;
    int t  = threadIdx.x;
    int tq = t & 31;                  // a-quad (a0 = tq*4)
    int rg = t >> 5;                  // warp -> rows rg*8..+7
    int js = t & 3;                   // staging k residue
    int rs = t >> 2;                  // staging row 0..31
    const int* rows = g_rows[p];
    const float* Wb = W1 + ((size_t)p * D_MODEL + (size_t)kz * KCH) * ADAPT;
    float* hp = g_hp[kz];
    unsigned wsb = (unsigned)__cvta_generic_to_shared(ws);

    for (int base = 0; base < n; base += RT) {
        int nn = min(RT, n - base);
        __syncthreads();              // previous tile fully consumed
        // prologue: weight stages 0..4 (each 4 KB = 256 float4, 2 per thread)
        #pragma unroll
        for (int s = 0; s < RING - 1; s++) {
            const float4* g = (const float4*)(Wb + (size_t)s * 8 * ADAPT);
            CP16(wsb + s * 4096u + (unsigned)t * 16u, g + t);
            CP16(wsb + s * 4096u + (unsigned)(t + 128) * 16u, g + t + 128);
            CPCOMMIT();
        }
        // stage x plain floats [k][row]; thread: row rs, k = js + 4c
        {
            const float* xr = (rs < nn)
                ? x + (size_t)rows[base + rs] * D_MODEL + kz * KCH : 0;
            #pragma unroll
            for (int c = 0; c < 32; c++) {
                int k = js + 4 * c;
                xs[k * RSF + rs] = (rs < nn) ? xr[k] : 0.f;
            }
        }
        ull acc[16];                  // [a 0..3][row-pair 0..3]
        #pragma unroll
        for (int j = 0; j < 16; j++) acc[j] = 0;
        bool active = (rg * 8 < nn);
        int cons = 0, prod = RING - 1;

        #pragma unroll 1
        for (int s = 0; s < NST; s++) {
            CPWAIT4();
            __syncthreads();
            if (s + RING - 1 < NST) {
                const float4* g = (const float4*)(Wb + (size_t)(s + RING - 1) * 8 * ADAPT);
                CP16(wsb + prod * 4096u + (unsigned)t * 16u, g + t);
                CP16(wsb + prod * 4096u + (unsigned)(t + 128) * 16u, g + t + 128);
            }
            CPCOMMIT();               // unconditional: uniform group indexing
            if (active) {
                const float* wl = ws + cons * (8 * ADAPT);
                const float* xb = xs + (s * 8) * RSF + rg * 8;
                #pragma unroll
                for (int kk = 0; kk < 8; kk++) {
                    float4 w = *(const float4*)(wl + kk * ADAPT + tq * 4);
                    ulonglong2 x01 = *(const ulonglong2*)(xb + kk * RSF);
                    ulonglong2 x23 = *(const ulonglong2*)(xb + kk * RSF + 4);
                    ull W0, W1d, W2d, W3d;
                    PACK2(W0, w.x); PACK2(W1d, w.y); PACK2(W2d, w.z); PACK2(W3d, w.w);
                    FMA2(acc[0],  W0,  x01.x, acc[0]);  FMA2(acc[1],  W0,  x01.y, acc[1]);
                    FMA2(acc[2],  W0,  x23.x, acc[2]);  FMA2(acc[3],  W0,  x23.y, acc[3]);
                    FMA2(acc[4],  W1d, x01.x, acc[4]);  FMA2(acc[5],  W1d, x01.y, acc[5]);
                    FMA2(acc[6],  W1d, x23.x, acc[6]);  FMA2(acc[7],  W1d, x23.y, acc[7]);
                    FMA2(acc[8],  W2d, x01.x, acc[8]);  FMA2(acc[9],  W2d, x01.y, acc[9]);
                    FMA2(acc[10], W2d, x23.x, acc[10]); FMA2(acc[11], W2d, x23.y, acc[11]);
                    FMA2(acc[12], W3d, x01.x, acc[12]); FMA2(acc[13], W3d, x01.y, acc[13]);
                    FMA2(acc[14], W3d, x23.x, acc[14]); FMA2(acc[15], W3d, x23.y, acc[15]);
                }
            }
            if (++cons == RING) cons = 0;
            if (++prod == RING) prod = 0;
        }
        // epilogue: transpose in-register -> coalesced float4 per row
        #pragma unroll
        for (int rp = 0; rp < 4; rp++) {
            float4 ve, vo;
            UNPK2(ve.x, vo.x, acc[0  + rp]);
            UNPK2(ve.y, vo.y, acc[4  + rp]);
            UNPK2(ve.z, vo.z, acc[8  + rp]);
            UNPK2(ve.w, vo.w, acc[12 + rp]);
            int r0 = rg * 8 + rp * 2;
            if (r0 < nn)
                *(float4*)(hp + (size_t)rows[base + r0] * ADAPT + tq * 4) = ve;
            if (r0 + 1 < nn)
                *(float4*)(hp + (size_t)rows[base + r0 + 1] * ADAPT + tq * 4) = vo;
        }
    }

    // ---- fused activation: last CTA of this pair reduces the 8 partials ----
    __threadfence();                  // make this CTA's hp stores visible
    __syncthreads();                  // all threads fenced
    if (t == 0) sticket = atomicAdd(&g_done[p], 1);
    __syncthreads();
    if (sticket == KC - 1) {
        __threadfence();              // order reads after the observed ticket
        float bb = b1[p * ADAPT + t];
        #pragma unroll 2
        for (int r = 0; r < n; r++) {
            size_t off = (size_t)rows[r] * ADAPT + t;
            float s0 = g_hp[0][off] + g_hp[1][off];
            float s1 = g_hp[2][off] + g_hp[3][off];
            float s2 = g_hp[4][off] + g_hp[5][off];
            float s3 = g_hp[6][off] + g_hp[7][off];
            g_h[off] = fmaxf((s0 + s1) + (s2 + s3) + bb, 0.f);
        }
    }
}

// ---------------------------------------------------------------------------
// GEMM2: out[row, d] = g_h[row,:] . W2[p,:,d] + b2[p,d]
// grid (64, 8), 128 thr. Same structure; d-quad tq, 8 rows per warp.
// ---------------------------------------------------------------------------
__global__ void __launch_bounds__(128, 5)
k_gemm2(const float* __restrict__ W2, const float* __restrict__ b2,
        float* __restrict__ out) {
    extern __shared__ __align__(16) char smx[];
    float* hs = (float*)smx;                      // [128 a][RSF] (18 KB)
    float* ws = (float*)(smx + ADAPT * RSF * 4);  // ring [6][8*128] (24 KB)
    int p  = blockIdx.x;
    int dc = blockIdx.y;
    int n = g_cnt[p];
    if (n == 0) return;
    int t  = threadIdx.x;
    int tq = t & 31;
    int rg = t >> 5;
    int js = t & 3;
    int rs = t >> 2;
    const int* rows = g_rows[p];
    const float* Wb = W2 + (size_t)p * ADAPT * D_MODEL + dc * DC;
    int d0 = dc * DC + tq * 4;
    float4 bias = *(const float4*)(b2 + (size_t)p * D_MODEL + d0);
    unsigned wsb = (unsigned)__cvta_generic_to_shared(ws);
    int wline = t >> 5;               // refill: lines (wline, wline+4), col = t&31
    int wcol  = t & 31;

    for (int base = 0; base < n; base += RT) {
        int nn = min(RT, n - base);
        __syncthreads();
        #pragma unroll
        for (int s = 0; s < RING - 1; s++) {
            CP16(wsb + s * 4096u + (unsigned)(wline * 32 + wcol) * 16u,
                 (const float4*)(Wb + (size_t)(s * 8 + wline) * D_MODEL) + wcol);
            CP16(wsb + s * 4096u + (unsigned)((wline + 4) * 32 + wcol) * 16u,
                 (const float4*)(Wb + (size_t)(s * 8 + wline + 4) * D_MODEL) + wcol);
            CPCOMMIT();
        }
        // stage h plain floats [a][row]
        {
            const float* hr = (rs < nn) ? g_h + (size_t)rows[base + rs] * ADAPT : 0;
            #pragma unroll
            for (int c = 0; c < 32; c++) {
                int a = js + 4 * c;
                hs[a * RSF + rs] = (rs < nn) ? hr[a] : 0.f;
            }
        }
        ull acc[16];
        #pragma unroll
        for (int j = 0; j < 16; j++) acc[j] = 0;
        bool active = (rg * 8 < nn);
        int cons = 0, prod = RING - 1;

        #pragma unroll 1
        for (int s = 0; s < NST; s++) {
            CPWAIT4();
            __syncthreads();
            if (s + RING - 1 < NST) {
                int sl = (s + RING - 1) * 8;
                CP16(wsb + prod * 4096u + (unsigned)(wline * 32 + wcol) * 16u,
                     (const float4*)(Wb + (size_t)(sl + wline) * D_MODEL) + wcol);
                CP16(wsb + prod * 4096u + (unsigned)((wline + 4) * 32 + wcol) * 16u,
                     (const float4*)(Wb + (size_t)(sl + wline + 4) * D_MODEL) + wcol);
            }
            CPCOMMIT();
            if (active) {
                const float* wl = ws + cons * (8 * DC);
                const float* hb = hs + (s * 8) * RSF + rg * 8;
                #pragma unroll
                for (int kk = 0; kk < 8; kk++) {
                    float4 w = *(const float4*)(wl + kk * DC + tq * 4);
                    ulonglong2 h01 = *(const ulonglong2*)(hb + kk * RSF);
                    ulonglong2 h23 = *(const ulonglong2*)(hb + kk * RSF + 4);
                    ull W0, W1d, W2d, W3d;
                    PACK2(W0, w.x); PACK2(W1d, w.y); PACK2(W2d, w.z); PACK2(W3d, w.w);
                    FMA2(acc[0],  W0,  h01.x, acc[0]);  FMA2(acc[1],  W0,  h01.y, acc[1]);
                    FMA2(acc[2],  W0,  h23.x, acc[2]);  FMA2(acc[3],  W0,  h23.y, acc[3]);
                    FMA2(acc[4],  W1d, h01.x, acc[4]);  FMA2(acc[5],  W1d, h01.y, acc[5]);
                    FMA2(acc[6],  W1d, h23.x, acc[6]);  FMA2(acc[7],  W1d, h23.y, acc[7]);
                    FMA2(acc[8],  W2d, h01.x, acc[8]);  FMA2(acc[9],  W2d, h01.y, acc[9]);
                    FMA2(acc[10], W2d, h23.x, acc[10]); FMA2(acc[11], W2d, h23.y, acc[11]);
                    FMA2(acc[12], W3d, h01.x, acc[12]); FMA2(acc[13], W3d, h01.y, acc[13]);
                    FMA2(acc[14], W3d, h23.x, acc[14]); FMA2(acc[15], W3d, h23.y, acc[15]);
                }
            }
            if (++cons == RING) cons = 0;
            if (++prod == RING) prod = 0;
        }
        #pragma unroll
        for (int rp = 0; rp < 4; rp++) {
            float4 ve, vo;
            UNPK2(ve.x, vo.x, acc[0  + rp]);
            UNPK2(ve.y, vo.y, acc[4  + rp]);
            UNPK2(ve.z, vo.z, acc[8  + rp]);
            UNPK2(ve.w, vo.w, acc[12 + rp]);
            ve.x += bias.x; ve.y += bias.y; ve.z += bias.z; ve.w += bias.w;
            vo.x += bias.x; vo.y += bias.y; vo.z += bias.z; vo.w += bias.w;
            int r0 = rg * 8 + rp * 2;
            if (r0 < nn)
                *(float4*)(out + (size_t)rows[base + r0] * D_MODEL + d0) = ve;
            if (r0 + 1 < nn)
                *(float4*)(out + (size_t)rows[base + r0 + 1] * D_MODEL + d0) = vo;
        }
    }
}

// ---------------------------------------------------------------------------
#define SMEM1 (KCH * RSF * 4 + RING * 8 * ADAPT * 4)   // 18432 + 24576 = 43008
#define SMEM2 (ADAPT * RSF * 4 + RING * 8 * DC * 4)    // 43008

extern "C" void kernel_launch(void* const* d_in, const int* in_sizes, int n_in,
                              void* d_out, int out_size) {
    const float* x   = (const float*)d_in[0];
    const int*   src = (const int*)d_in[1];
    const int*   tgt = (const int*)d_in[2];
    const float* W1  = (const float*)d_in[3];
    const float* b1  = (const float*)d_in[4];
    const float* W2  = (const float*)d_in[5];
    const float* b2  = (const float*)d_in[6];
    float* out = (float*)d_out;
    int B = in_sizes[1];  // 1024

    cudaFuncSetAttribute(k_gemm1, cudaFuncAttributeMaxDynamicSharedMemorySize, SMEM1);
    cudaFuncSetAttribute(k_gemm2, cudaFuncAttributeMaxDynamicSharedMemorySize, SMEM2);

    k_build<<<1, 1024>>>(src, tgt, B);
    k_copy<<<256, 256>>>(x, src, tgt, out, B);
    k_gemm1<<<dim3(NPAIR, KC), 128, SMEM1>>>(x, W1, b1);
    k_gemm2<<<dim3(NPAIR, 8), 128, SMEM2>>>(W2, b2, out);
}

// round 13
// speedup vs baseline: 1.0491x; 1.0491x over previous
#include <cuda_runtime.h>

// Problem constants (fixed by dataset)
#define D_MODEL 1024
#define ADAPT   128
#define NUM_LIB 8
#define NPAIR   64
#define MAXB    1024
#define KC      8        // k-split for gemm1 (128 k per CTA)
#define KCH     128
#define DC      128      // d-cols per gemm2 CTA
#define NST     16       // stages per slab (8 lines x 128 cols = 4 KB each)
#define RT      32       // row capacity per tile (covers whole pair)
#define RING    6        // cp.async ring depth

typedef unsigned long long ull;

// Packed fp32x2 ops (sm_10x)
#define FMA2(d,a,b,c) asm("fma.rn.f32x2 %0, %1, %2, %3;":"=l"(d):"l"(a),"l"(b),"l"(c))
#define PACK2(d,s)    asm("mov.b64 %0, {%1, %1};":"=l"(d):"f"(s))
// cp.async 16B, L1-bypass
#define CP16(dst,src) asm volatile("cp.async.cg.shared.global [%0], [%1], 16;"::"r"(dst),"l"(src))
#define CPCOMMIT()    asm volatile("cp.async.commit_group;")
#define CPWAIT4()     asm volatile("cp.async.wait_group 4;")

// Device scratch (no allocations allowed)
__device__ int   g_cnt[NPAIR];
__device__ int   g_rows[NPAIR][MAXB];
__device__ float g_hp[KC][MAXB * ADAPT];   // K-split partial pre-activations
__device__ float g_h[MAXB * ADAPT];        // relu(sum + b1)

// ---------------------------------------------------------------------------
__global__ void k_build(const int* __restrict__ src, const int* __restrict__ tgt, int B) {
    int t = threadIdx.x;
    if (t < NPAIR) g_cnt[t] = 0;
    __syncthreads();
    if (t < B) {
        int s = src[t], g = tgt[t];
        if (s != g) {
            int p = s * NUM_LIB + g;
            int slot = atomicAdd(&g_cnt[p], 1);
            g_rows[p][slot] = t;
        }
    }
}

// ---------------------------------------------------------------------------
__global__ void __launch_bounds__(256)
k_copy(const float* __restrict__ x,
       const int* __restrict__ src, const int* __restrict__ tgt,
       float* __restrict__ out, int B) {
    for (int b = blockIdx.x; b < B; b += gridDim.x) {
        if (src[b] != tgt[b]) continue;
        const float4* xi = (const float4*)(x + (size_t)b * D_MODEL);
        float4* yo = (float4*)(out + (size_t)b * D_MODEL);
        yo[threadIdx.x] = xi[threadIdx.x];
    }
}

// ---------------------------------------------------------------------------
// k_act: g_h = relu(sum_kz g_hp + b1). 256 CTAs x 256 thr, one float2 each.
// ---------------------------------------------------------------------------
__global__ void __launch_bounds__(256)
k_act(const int* __restrict__ src, const int* __restrict__ tgt,
      const float* __restrict__ b1) {
    int idx = blockIdx.x * 256 + threadIdx.x;   // over 65536 float2
    int row = idx >> 6;
    int q   = idx & 63;
    int s = src[row], g = tgt[row];
    if (s == g) return;
    int p = s * NUM_LIB + g;
    size_t off = (size_t)row * ADAPT + q * 2;
    float2 v = make_float2(0.f, 0.f);
    #pragma unroll
    for (int kz = 0; kz < KC; kz++) {
        float2 u = *(const float2*)(g_hp[kz] + off);
        v.x += u.x; v.y += u.y;
    }
    float2 b = *(const float2*)(b1 + p * ADAPT + q * 2);
    v.x = fmaxf(v.x + b.x, 0.f);
    v.y = fmaxf(v.y + b.y, 0.f);
    *(float2*)(g_h + off) = v;
}

// ---------------------------------------------------------------------------
// GEMM1 (k-split): g_hp[kz][row, a] = x[row, kz*128:+128] . W1[p, slice, a]
// grid (64, 8), 128 thr. Thread: a-quad tq = t&31, warp rg = t>>5 -> 8 rows.
// x duplicated as f32x2 in smem [k][32 rows] (broadcast reads); weights
// naturally packed along a via LDS.128 -> inner: 5 LDS + 16 FMA2 / 32 MACs.
// Depth-6 cp.async weight ring (wait_group 4).
// ---------------------------------------------------------------------------
__global__ void __launch_bounds__(128, 4)
k_gemm1(const float* __restrict__ x, const float* __restrict__ W1) {
    extern __shared__ __align__(16) char smx[];
    ull*   xs2 = (ull*)smx;                       // [128 k][32 r] dup pairs (32 KB)
    float* ws  = (float*)(smx + KCH * RT * 8);    // ring [6][8*128] (24 KB)
    int p  = blockIdx.x;
    int kz = blockIdx.y;
    int n = g_cnt[p];
    if (n == 0) return;
    int t  = threadIdx.x;
    int tq = t & 31;                  // a-quad (a0 = tq*4)
    int rg = t >> 5;                  // warp -> rows rg*8..+7
    int js = t & 3;                   // staging k residue
    int rs = t >> 2;                  // staging row 0..31
    const int* rows = g_rows[p];
    const float* Wb = W1 + ((size_t)p * D_MODEL + (size_t)kz * KCH) * ADAPT;
    float* hp = g_hp[kz];
    unsigned wsb = (unsigned)__cvta_generic_to_shared(ws);

    for (int base = 0; base < n; base += RT) {
        int nn = min(RT, n - base);
        __syncthreads();              // previous tile fully consumed
        // prologue: weight stages 0..4 (each 4 KB = 256 float4, 2 per thread)
        #pragma unroll
        for (int s = 0; s < RING - 1; s++) {
            const float4* g = (const float4*)(Wb + (size_t)s * 8 * ADAPT);
            CP16(wsb + s * 4096u + (unsigned)t * 16u, g + t);
            CP16(wsb + s * 4096u + (unsigned)(t + 128) * 16u, g + t + 128);
            CPCOMMIT();
        }
        // stage x dup pairs [k][row]; thread: row rs, k = js + 4c
        {
            const float* xr = (rs < nn)
                ? x + (size_t)rows[base + rs] * D_MODEL + kz * KCH : 0;
            #pragma unroll
            for (int c = 0; c < 32; c++) {
                int k = js + 4 * c;
                float v = (rs < nn) ? xr[k] : 0.f;
                ull vd; PACK2(vd, v);
                xs2[k * RT + rs] = vd;
            }
        }
        ull accA[8], accB[8];         // apair0/apair1 x rows 0..7
        #pragma unroll
        for (int j = 0; j < 8; j++) { accA[j] = 0; accB[j] = 0; }
        bool active = (rg * 8 < nn);
        int cons = 0, prod = RING - 1;

        #pragma unroll 1
        for (int s = 0; s < NST; s++) {
            CPWAIT4();
            __syncthreads();
            if (s + RING - 1 < NST) {
                const float4* g = (const float4*)(Wb + (size_t)(s + RING - 1) * 8 * ADAPT);
                CP16(wsb + prod * 4096u + (unsigned)t * 16u, g + t);
                CP16(wsb + prod * 4096u + (unsigned)(t + 128) * 16u, g + t + 128);
            }
            CPCOMMIT();               // unconditional: uniform group indexing
            if (active) {
                const float* wl = ws + cons * (8 * ADAPT);
                const ull* xb = xs2 + (s * 8) * RT + rg * 8;
                #pragma unroll
                for (int kk = 0; kk < 8; kk++) {
                    ulonglong2 w = *(const ulonglong2*)(wl + kk * ADAPT + tq * 4);
                    const ull* xr8 = xb + kk * RT;
                    ulonglong2 x01 = *(const ulonglong2*)(xr8);
                    ulonglong2 x23 = *(const ulonglong2*)(xr8 + 2);
                    ulonglong2 x45 = *(const ulonglong2*)(xr8 + 4);
                    ulonglong2 x67 = *(const ulonglong2*)(xr8 + 6);
                    FMA2(accA[0], w.x, x01.x, accA[0]); FMA2(accB[0], w.y, x01.x, accB[0]);
                    FMA2(accA[1], w.x, x01.y, accA[1]); FMA2(accB[1], w.y, x01.y, accB[1]);
                    FMA2(accA[2], w.x, x23.x, accA[2]); FMA2(accB[2], w.y, x23.x, accB[2]);
                    FMA2(accA[3], w.x, x23.y, accA[3]); FMA2(accB[3], w.y, x23.y, accB[3]);
                    FMA2(accA[4], w.x, x45.x, accA[4]); FMA2(accB[4], w.y, x45.x, accB[4]);
                    FMA2(accA[5], w.x, x45.y, accA[5]); FMA2(accB[5], w.y, x45.y, accB[5]);
                    FMA2(accA[6], w.x, x67.x, accA[6]); FMA2(accB[6], w.y, x67.x, accB[6]);
                    FMA2(accA[7], w.x, x67.y, accA[7]); FMA2(accB[7], w.y, x67.y, accB[7]);
                }
            }
            if (++cons == RING) cons = 0;
            if (++prod == RING) prod = 0;
        }
        // epilogue: acc is a-packed -> direct float4 store per row
        #pragma unroll
        for (int j = 0; j < 8; j++) {
            int r = rg * 8 + j;
            if (r < nn) {
                ulonglong2 sv; sv.x = accA[j]; sv.y = accB[j];
                *(ulonglong2*)(hp + (size_t)rows[base + r] * ADAPT + tq * 4) = sv;
            }
        }
    }
}

// ---------------------------------------------------------------------------
// GEMM2: out[row, d] = g_h[row,:] . W2[p,:,d] + b2[p,d]
// grid (64, 8), 128 thr. Same structure; d-quad tq, 8 rows per warp.
// ---------------------------------------------------------------------------
__global__ void __launch_bounds__(128, 4)
k_gemm2(const float* __restrict__ W2, const float* __restrict__ b2,
        float* __restrict__ out) {
    extern __shared__ __align__(16) char smx[];
    ull*   hs2 = (ull*)smx;                       // [128 a][32 r] dup pairs (32 KB)
    float* ws  = (float*)(smx + ADAPT * RT * 8);  // ring [6][8*128] (24 KB)
    int p  = blockIdx.x;
    int dc = blockIdx.y;
    int n = g_cnt[p];
    if (n == 0) return;
    int t  = threadIdx.x;
    int tq = t & 31;
    int rg = t >> 5;
    int js = t & 3;
    int rs = t >> 2;
    const int* rows = g_rows[p];
    const float* Wb = W2 + (size_t)p * ADAPT * D_MODEL + dc * DC;
    int d0 = dc * DC + tq * 4;
    float4 bias = *(const float4*)(b2 + (size_t)p * D_MODEL + d0);
    unsigned wsb = (unsigned)__cvta_generic_to_shared(ws);
    int wline = t >> 5;               // refill: lines (wline, wline+4), col = t&31
    int wcol  = t & 31;

    for (int base = 0; base < n; base += RT) {
        int nn = min(RT, n - base);
        __syncthreads();
        #pragma unroll
        for (int s = 0; s < RING - 1; s++) {
            CP16(wsb + s * 4096u + (unsigned)(wline * 32 + wcol) * 16u,
                 (const float4*)(Wb + (size_t)(s * 8 + wline) * D_MODEL) + wcol);
            CP16(wsb + s * 4096u + (unsigned)((wline + 4) * 32 + wcol) * 16u,
                 (const float4*)(Wb + (size_t)(s * 8 + wline + 4) * D_MODEL) + wcol);
            CPCOMMIT();
        }
        // stage h dup pairs [a][row]
        {
            const float* hr = (rs < nn) ? g_h + (size_t)rows[base + rs] * ADAPT : 0;
            #pragma unroll
            for (int c = 0; c < 32; c++) {
                int a = js + 4 * c;
                float v = (rs < nn) ? hr[a] : 0.f;
                ull vd; PACK2(vd, v);
                hs2[a * RT + rs] = vd;
            }
        }
        ull accA[8], accB[8];
        #pragma unroll
        for (int j = 0; j < 8; j++) { accA[j] = 0; accB[j] = 0; }
        bool active = (rg * 8 < nn);
        int cons = 0, prod = RING - 1;

        #pragma unroll 1
        for (int s = 0; s < NST; s++) {
            CPWAIT4();
            __syncthreads();
            if (s + RING - 1 < NST) {
                int sl = (s + RING - 1) * 8;
                CP16(wsb + prod * 4096u + (unsigned)(wline * 32 + wcol) * 16u,
                     (const float4*)(Wb + (size_t)(sl + wline) * D_MODEL) + wcol);
                CP16(wsb + prod * 4096u + (unsigned)((wline + 4) * 32 + wcol) * 16u,
                     (const float4*)(Wb + (size_t)(sl + wline + 4) * D_MODEL) + wcol);
            }
            CPCOMMIT();
            if (active) {
                const float* wl = ws + cons * (8 * DC);
                const ull* hb = hs2 + (s * 8) * RT + rg * 8;
                #pragma unroll
                for (int kk = 0; kk < 8; kk++) {
                    ulonglong2 w = *(const ulonglong2*)(wl + kk * DC + tq * 4);
                    const ull* hr8 = hb + kk * RT;
                    ulonglong2 h01 = *(const ulonglong2*)(hr8);
                    ulonglong2 h23 = *(const ulonglong2*)(hr8 + 2);
                    ulonglong2 h45 = *(const ulonglong2*)(hr8 + 4);
                    ulonglong2 h67 = *(const ulonglong2*)(hr8 + 6);
                    FMA2(accA[0], w.x, h01.x, accA[0]); FMA2(accB[0], w.y, h01.x, accB[0]);
                    FMA2(accA[1], w.x, h01.y, accA[1]); FMA2(accB[1], w.y, h01.y, accB[1]);
                    FMA2(accA[2], w.x, h23.x, accA[2]); FMA2(accB[2], w.y, h23.x, accB[2]);
                    FMA2(accA[3], w.x, h23.y, accA[3]); FMA2(accB[3], w.y, h23.y, accB[3]);
                    FMA2(accA[4], w.x, h45.x, accA[4]); FMA2(accB[4], w.y, h45.x, accB[4]);
                    FMA2(accA[5], w.x, h45.y, accA[5]); FMA2(accB[5], w.y, h45.y, accB[5]);
                    FMA2(accA[6], w.x, h67.x, accA[6]); FMA2(accB[6], w.y, h67.x, accB[6]);
                    FMA2(accA[7], w.x, h67.y, accA[7]); FMA2(accB[7], w.y, h67.y, accB[7]);
                }
            }
            if (++cons == RING) cons = 0;
            if (++prod == RING) prod = 0;
        }
        #pragma unroll
        for (int j = 0; j < 8; j++) {
            int r = rg * 8 + j;
            if (r < nn) {
                ulonglong2 sv; sv.x = accA[j]; sv.y = accB[j];
                float4 f = *(float4*)&sv;
                f.x += bias.x; f.y += bias.y; f.z += bias.z; f.w += bias.w;
                *(float4*)(out + (size_t)rows[base + r] * D_MODEL + d0) = f;
            }
        }
    }
}

// ---------------------------------------------------------------------------
#define SMEM1 (KCH * RT * 8 + RING * 8 * ADAPT * 4)   // 32768 + 24576 = 57344
#define SMEM2 (ADAPT * RT * 8 + RING * 8 * DC * 4)    // 57344

extern "C" void kernel_launch(void* const* d_in, const int* in_sizes, int n_in,
                              void* d_out, int out_size) {
    const float* x   = (const float*)d_in[0];
    const int*   src = (const int*)d_in[1];
    const int*   tgt = (const int*)d_in[2];
    const float* W1  = (const float*)d_in[3];
    const float* b1  = (const float*)d_in[4];
    const float* W2  = (const float*)d_in[5];
    const float* b2  = (const float*)d_in[6];
    float* out = (float*)d_out;
    int B = in_sizes[1];  // 1024

    cudaFuncSetAttribute(k_gemm1, cudaFuncAttributeMaxDynamicSharedMemorySize, SMEM1);
    cudaFuncSetAttribute(k_gemm2, cudaFuncAttributeMaxDynamicSharedMemorySize, SMEM2);

    k_build<<<1, 1024>>>(src, tgt, B);
    k_copy<<<256, 256>>>(x, src, tgt, out, B);
    k_gemm1<<<dim3(NPAIR, KC), 128, SMEM1>>>(x, W1);
    k_act<<<256, 256>>>(src, tgt, b1);
    k_gemm2<<<dim3(NPAIR, 8), 128, SMEM2>>>(W2, b2, out);
}